// round 9
// baseline (speedup 1.0000x reference)
#include <cuda_runtime.h>
#include <cuda_bf16.h>
#include <cstdint>

#define NN 50000
#define KK 16
#define DD 256
#define LN_EPS 1e-5f

#define BM 64
#define NTILES 782          // ceil(50000/64)

// ---------------- device scratch ----------------
// W^T split: [n=256][k=256] bf16 => 32 uint4 per row (row.col B operand)
__device__ uint4 g_wh[(size_t)256 * 32];
__device__ uint4 g_wl[(size_t)256 * 32];

#define SWZ(off) ((off) ^ (((off) >> 3) & 0x70))

__device__ __forceinline__ uint32_t smem_to_u32(const void* p) {
    uint32_t a;
    asm("{ .reg .u64 t; cvta.to.shared.u64 t, %1; cvt.u32.u64 %0, t; }" : "=r"(a) : "l"(p));
    return a;
}
__device__ __forceinline__ void ldsm_x4(uint32_t addr, uint32_t* r) {
    asm volatile("ldmatrix.sync.aligned.m8n8.x4.shared.b16 {%0,%1,%2,%3}, [%4];"
                 : "=r"(r[0]), "=r"(r[1]), "=r"(r[2]), "=r"(r[3]) : "r"(addr));
}
__device__ __forceinline__ void mma16816(float* c, const uint32_t* a, uint32_t b0, uint32_t b1) {
    asm volatile("mma.sync.aligned.m16n8k16.row.col.f32.bf16.bf16.f32 "
                 "{%0,%1,%2,%3}, {%4,%5,%6,%7}, {%8,%9}, {%0,%1,%2,%3};"
                 : "+f"(c[0]), "+f"(c[1]), "+f"(c[2]), "+f"(c[3])
                 : "r"(a[0]), "r"(a[1]), "r"(a[2]), "r"(a[3]), "r"(b0), "r"(b1));
}
__device__ __forceinline__ void split2(float v0, float v1, unsigned& hi, unsigned& lo) {
    __nv_bfloat16 h0 = __float2bfloat16_rn(v0);
    __nv_bfloat16 h1 = __float2bfloat16_rn(v1);
    __nv_bfloat16 l0 = __float2bfloat16_rn(v0 - __bfloat162float(h0));
    __nv_bfloat16 l1 = __float2bfloat16_rn(v1 - __bfloat162float(h1));
    hi = ((unsigned)__bfloat16_as_ushort(h1) << 16) | (unsigned)__bfloat16_as_ushort(h0);
    lo = ((unsigned)__bfloat16_as_ushort(l1) << 16) | (unsigned)__bfloat16_as_ushort(l0);
}

// ---------------------------------------------------------------------------
// Kernel 1: split + transpose W [k][n] fp32 -> g_wh/g_wl [n][k] bf16
// ---------------------------------------------------------------------------
__global__ void __launch_bounds__(256) wprep_kernel(const float* __restrict__ W)
{
    int idx = blockIdx.x * 256 + threadIdx.x;   // idx = n*256 + k
    int n = idx >> 8, k = idx & 255;
    float v = W[(size_t)k * 256 + n];
    __nv_bfloat16 h = __float2bfloat16_rn(v);
    __nv_bfloat16 l = __float2bfloat16_rn(v - __bfloat162float(h));
    reinterpret_cast<unsigned short*>(g_wh)[idx] = __bfloat16_as_ushort(h);
    reinterpret_cast<unsigned short*>(g_wl)[idx] = __bfloat16_as_ushort(l);
}

// ---------------------------------------------------------------------------
// Kernel 2: FUSED gather + HMMA GEMM (3-term bf16 split) + LayerNorm.
// CTA = 64 nodes, 256 threads (8 warps), 2 CTAs/SM.
//   Phase 1: each warp gathers 8 nodes straight into swizzled smem A (hi/lo).
//   Phase 2: per K-chunk(64): load B_hi -> {hh, lh} MMAs; load B_lo -> {hl}.
//            Single 32 KB B buffer (reuse keeps smem <= 96KB+const).
//   Phase 3: fused LN epilogue (quad shuffle + smem cross-warp combine).
// Warp grid 2(m) x 4(n); warp tile 32x64; 64 fp32 accums/thread.
// ---------------------------------------------------------------------------
#define SMO_AH 0                        // 4 chunks x 8192 B (64 rows x 128B)
#define SMO_AL 32768                    // 4 chunks x 8192 B
#define SMO_B  65536                    // 32768 B (one half: hi OR lo)
#define SMO_CONST 98304                 // bias/gamma/beta: 3 x 1KB
#define SMEM_TOTAL (SMO_CONST + 3072)   // 101376 B -> 2 CTAs/SM
// epilogue overlays A region: psum float2[4][64] @0, stats float2[64] @2048

__global__ void __launch_bounds__(256, 2) fused_kernel(
    const float* __restrict__ feats,
    const int*   __restrict__ nbr,
    const float* __restrict__ iw,
    const float* __restrict__ bias,
    const float* __restrict__ gamma,
    const float* __restrict__ beta,
    float* __restrict__ out)
{
    extern __shared__ char smem[];
    const uint32_t sb = smem_to_u32(smem);
    const int tid  = threadIdx.x;
    const int wid  = tid >> 5;
    const int lane = tid & 31;
    const int wm   = wid >> 2;          // 0..1 (m)
    const int wn   = wid & 3;           // 0..3 (n)
    const int row0 = blockIdx.x * BM;

    float* sC = reinterpret_cast<float*>(smem + SMO_CONST);
    if (tid < 256) {
        sC[tid]       = bias[tid];
        sC[256 + tid] = gamma[tid];
        sC[512 + tid] = beta[tid];
    }

    // ================= Phase 1: gather 64 nodes into smem A =================
    {
        const int ch0   = lane >> 4;            // a0 -> chunk 0/1, a1 -> 2/3
        const int inner = (lane & 15) * 8;      // byte offset within 128B row
        #pragma unroll 1
        for (int i = 0; i < 8; i++) {
            int r    = wid * 8 + i;             // local row 0..63
            int node = row0 + r;
            bool valid = node < NN;

            float w = 0.0f;  int idx = 0;
            if (valid && lane < KK) {
                w   = iw[node * KK + lane];
                idx = nbr[node * KK + lane];
            }
            float wsum = w;
            #pragma unroll
            for (int o = 16; o >= 1; o >>= 1)
                wsum += __shfl_xor_sync(0xffffffffu, wsum, o);
            float weff = (wsum == 0.0f) ? (1.0f / KK) : (w / wsum);

            float4 a0 = make_float4(0.f, 0.f, 0.f, 0.f);
            float4 a1 = make_float4(0.f, 0.f, 0.f, 0.f);
            if (valid) {
                #pragma unroll
                for (int k = 0; k < KK; k++) {
                    float wk = __shfl_sync(0xffffffffu, weff, k);
                    int   nk = __shfl_sync(0xffffffffu, idx,  k);
                    const float4* rp = reinterpret_cast<const float4*>(feats + (size_t)nk * DD);
                    float4 f0 = __ldg(rp + lane);
                    float4 f1 = __ldg(rp + lane + 32);
                    a0.x += wk * f0.x; a0.y += wk * f0.y; a0.z += wk * f0.z; a0.w += wk * f0.w;
                    a1.x += wk * f1.x; a1.y += wk * f1.y; a1.z += wk * f1.z; a1.w += wk * f1.w;
                }
            }
            uint32_t so = SWZ((uint32_t)(r * 128 + inner));
            uint2 h, l;
            split2(a0.x, a0.y, h.x, l.x); split2(a0.z, a0.w, h.y, l.y);
            *reinterpret_cast<uint2*>(smem + SMO_AH + ch0 * 8192 + so) = h;
            *reinterpret_cast<uint2*>(smem + SMO_AL + ch0 * 8192 + so) = l;
            split2(a1.x, a1.y, h.x, l.x); split2(a1.z, a1.w, h.y, l.y);
            *reinterpret_cast<uint2*>(smem + SMO_AH + (2 + ch0) * 8192 + so) = h;
            *reinterpret_cast<uint2*>(smem + SMO_AL + (2 + ch0) * 8192 + so) = l;
        }
    }

    // ================= Phase 2: HMMA mainloop =================
    float c[2][8][4];
    #pragma unroll
    for (int i = 0; i < 2; i++)
        #pragma unroll
        for (int j = 0; j < 8; j++)
            #pragma unroll
            for (int q = 0; q < 4; q++) c[i][j][q] = 0.f;

    const int lrow = lane & 15;
    const int lkb  = (lane >> 4) * 16;

    for (int ch = 0; ch < 4; ch++) {
        #pragma unroll
        for (int half = 0; half < 2; half++) {
            __syncthreads();   // prev MMA's ldsm done (also: phase-1 A visible)
            // load B half-chunk: 256 rows x 64 bf16 = 2048 uint4
            const uint4* gsrc = half ? g_wl : g_wh;
            #pragma unroll
            for (int i = 0; i < 8; i++) {
                int e = tid + i * 256;
                int r = e >> 3, q = e & 7;
                uint32_t so = SWZ((uint32_t)(r * 128 + q * 16));
                *reinterpret_cast<uint4*>(smem + SMO_B + so) = gsrc[(size_t)r * 32 + ch * 8 + q];
            }
            __syncthreads();

            #pragma unroll
            for (int ks = 0; ks < 4; ks++) {
                const int kb = ks * 32 + lkb;
                uint32_t ah[2][4], al[2][4];
                #pragma unroll
                for (int mm = 0; mm < 2; mm++) {
                    uint32_t off = SWZ((uint32_t)((wm * 32 + mm * 16 + lrow) * 128 + kb));
                    ldsm_x4(sb + SMO_AH + ch * 8192 + off, ah[mm]);
                    if (!half) ldsm_x4(sb + SMO_AL + ch * 8192 + off, al[mm]);
                }
                #pragma unroll
                for (int np = 0; np < 4; np++) {
                    uint32_t off = SWZ((uint32_t)((wn * 64 + np * 16 + lrow) * 128 + kb));
                    uint32_t b[4];
                    ldsm_x4(sb + SMO_B + off, b);
                    #pragma unroll
                    for (int sub = 0; sub < 2; sub++) {
                        int mn = np * 2 + sub;
                        #pragma unroll
                        for (int mm = 0; mm < 2; mm++) {
                            mma16816(c[mm][mn], ah[mm], b[sub], b[2 + sub]);   // hh or hl
                            if (!half)
                                mma16816(c[mm][mn], al[mm], b[sub], b[2 + sub]); // lh
                        }
                    }
                }
            }
        }
    }
    __syncthreads();   // tiles dead; smem reused for LN reductions

    // ================= Phase 3: +bias, fused LayerNorm =================
    const int q2 = 2 * (lane & 3);
    #pragma unroll
    for (int mm = 0; mm < 2; mm++)
        #pragma unroll
        for (int mn = 0; mn < 8; mn++) {
            int col = wn * 64 + mn * 8 + q2;
            float b0 = sC[col], b1 = sC[col + 1];
            c[mm][mn][0] += b0; c[mm][mn][1] += b1;
            c[mm][mn][2] += b0; c[mm][mn][3] += b1;
        }

    float2* psum  = reinterpret_cast<float2*>(smem);          // [wn*64 + row]
    float2* stats = reinterpret_cast<float2*>(smem + 2048);   // [row]

    #pragma unroll
    for (int mm = 0; mm < 2; mm++) {
        #pragma unroll
        for (int h = 0; h < 2; h++) {
            float s = 0.f, s2 = 0.f;
            #pragma unroll
            for (int mn = 0; mn < 8; mn++) {
                float v0 = c[mm][mn][h * 2 + 0];
                float v1 = c[mm][mn][h * 2 + 1];
                s += v0 + v1;  s2 += v0 * v0 + v1 * v1;
            }
            s  += __shfl_xor_sync(0xffffffffu, s, 1);
            s  += __shfl_xor_sync(0xffffffffu, s, 2);
            s2 += __shfl_xor_sync(0xffffffffu, s2, 1);
            s2 += __shfl_xor_sync(0xffffffffu, s2, 2);
            if ((lane & 3) == 0) {
                int row = wm * 32 + mm * 16 + h * 8 + (lane >> 2);
                psum[wn * 64 + row] = make_float2(s, s2);
            }
        }
    }
    __syncthreads();

    if (tid < 64) {
        float s = 0.f, s2 = 0.f;
        #pragma unroll
        for (int p = 0; p < 4; p++) {
            float2 v = psum[p * 64 + tid];
            s += v.x;  s2 += v.y;
        }
        float mean = s * (1.0f / 256.0f);
        float var  = s2 * (1.0f / 256.0f) - mean * mean;
        stats[tid] = make_float2(mean, rsqrtf(var + LN_EPS));
    }
    __syncthreads();

    #pragma unroll
    for (int mm = 0; mm < 2; mm++)
        #pragma unroll
        for (int h = 0; h < 2; h++) {
            int row  = wm * 32 + mm * 16 + h * 8 + (lane >> 2);
            int grow = row0 + row;
            if (grow >= NN) continue;
            float2 st = stats[row];
            #pragma unroll
            for (int mn = 0; mn < 8; mn++) {
                int col = wn * 64 + mn * 8 + q2;
                float v0 = (c[mm][mn][h * 2 + 0] - st.x) * st.y * sC[256 + col]     + sC[512 + col];
                float v1 = (c[mm][mn][h * 2 + 1] - st.x) * st.y * sC[256 + col + 1] + sC[512 + col + 1];
                *reinterpret_cast<float2*>(out + (size_t)grow * DD + col) = make_float2(v0, v1);
            }
        }
}

// ---------------------------------------------------------------------------
extern "C" void kernel_launch(void* const* d_in, const int* in_sizes, int n_in,
                              void* d_out, int out_size)
{
    const float* feats = (const float*)d_in[0];
    const int*   nbr   = (const int*)d_in[1];    // int32 (JAX x64 disabled)
    const float* iw    = (const float*)d_in[2];
    const float* Wm    = (const float*)d_in[3];
    const float* bias  = (const float*)d_in[4];
    const float* gamma = (const float*)d_in[5];
    const float* beta  = (const float*)d_in[6];
    float*       out   = (float*)d_out;

    cudaFuncSetAttribute(fused_kernel,
                         cudaFuncAttributeMaxDynamicSharedMemorySize, SMEM_TOTAL);

    wprep_kernel<<<256, 256>>>(Wm);
    fused_kernel<<<NTILES, 256, SMEM_TOTAL>>>(feats, nbr, iw, bias, gamma, beta, out);
}

// round 11
// speedup vs baseline: 1.6463x; 1.6463x over previous
#include <cuda_runtime.h>
#include <cuda_bf16.h>
#include <cstdint>

#define NN 50000
#define KK 16
#define DD 256
#define LN_EPS 1e-5f

#define NTILES 391          // ceil(50000/128)
#define NPAD   (NTILES*128) // 50048

// ---------------- device scratch (zero-initialized at load) ----------------
// z split into bf16 hi/lo, [NPAD][256] bf16 each => 32 uint4 per row
__device__ uint4 g_ah[(size_t)NPAD * 32];
__device__ uint4 g_al[(size_t)NPAD * 32];
// W^T split: [n=256][k=256] bf16 => 32 uint4 per row (row.col B operand)
__device__ uint4 g_wh[(size_t)256 * 32];
__device__ uint4 g_wl[(size_t)256 * 32];

#define SWZ(off) ((off) ^ (((off) >> 3) & 0x70))

__device__ __forceinline__ uint32_t smem_to_u32(const void* p) {
    uint32_t a;
    asm("{ .reg .u64 t; cvta.to.shared.u64 t, %1; cvt.u32.u64 %0, t; }" : "=r"(a) : "l"(p));
    return a;
}
__device__ __forceinline__ void ldsm_x4(uint32_t addr, uint32_t* r) {
    asm volatile("ldmatrix.sync.aligned.m8n8.x4.shared.b16 {%0,%1,%2,%3}, [%4];"
                 : "=r"(r[0]), "=r"(r[1]), "=r"(r[2]), "=r"(r[3]) : "r"(addr));
}
__device__ __forceinline__ void mma16816(float* c, const uint32_t* a, uint32_t b0, uint32_t b1) {
    asm volatile("mma.sync.aligned.m16n8k16.row.col.f32.bf16.bf16.f32 "
                 "{%0,%1,%2,%3}, {%4,%5,%6,%7}, {%8,%9}, {%0,%1,%2,%3};"
                 : "+f"(c[0]), "+f"(c[1]), "+f"(c[2]), "+f"(c[3])
                 : "r"(a[0]), "r"(a[1]), "r"(a[2]), "r"(a[3]), "r"(b0), "r"(b1));
}
__device__ __forceinline__ void cpasync16(uint32_t dst, const void* src) {
    asm volatile("cp.async.cg.shared.global [%0], [%1], 16;" :: "r"(dst), "l"(src));
}
#define CP_COMMIT() asm volatile("cp.async.commit_group;" ::: "memory")
#define CP_WAIT(n)  asm volatile("cp.async.wait_group %0;" :: "n"(n) : "memory")

__device__ __forceinline__ void split2(float v0, float v1, unsigned& hi, unsigned& lo) {
    __nv_bfloat16 h0 = __float2bfloat16_rn(v0);
    __nv_bfloat16 h1 = __float2bfloat16_rn(v1);
    __nv_bfloat16 l0 = __float2bfloat16_rn(v0 - __bfloat162float(h0));
    __nv_bfloat16 l1 = __float2bfloat16_rn(v1 - __bfloat162float(h1));
    hi = ((unsigned)__bfloat16_as_ushort(h1) << 16) | (unsigned)__bfloat16_as_ushort(h0);
    lo = ((unsigned)__bfloat16_as_ushort(l1) << 16) | (unsigned)__bfloat16_as_ushort(l0);
}

// ---------------------------------------------------------------------------
// Kernel 1: weighted neighbor gather -> z, emitted as split bf16 hi/lo.
// One warp per node; coalesced 128B row loads. neighbors are int32.
// Blocks 0..255 ALSO split+transpose one W element per thread (wprep merged).
// ---------------------------------------------------------------------------
__global__ void __launch_bounds__(256) gather_kernel(
    const float* __restrict__ feats,
    const int*   __restrict__ nbr,
    const float* __restrict__ iw,
    const float* __restrict__ W)
{
    // ---- merged wprep: W [k][n] fp32 -> g_wh/g_wl [n][k] bf16 ----
    if (blockIdx.x < 256) {
        int idx = blockIdx.x * 256 + threadIdx.x;   // idx = n*256 + k
        int n = idx >> 8, k = idx & 255;
        float v = W[(size_t)k * 256 + n];
        __nv_bfloat16 h = __float2bfloat16_rn(v);
        __nv_bfloat16 l = __float2bfloat16_rn(v - __bfloat162float(h));
        reinterpret_cast<unsigned short*>(g_wh)[idx] = __bfloat16_as_ushort(h);
        reinterpret_cast<unsigned short*>(g_wl)[idx] = __bfloat16_as_ushort(l);
    }

    int warp = blockIdx.x * (blockDim.x >> 5) + (threadIdx.x >> 5);
    int lane = threadIdx.x & 31;
    if (warp >= NN) return;

    float w = 0.0f;
    int idx = 0;
    if (lane < KK) {
        w   = iw[warp * KK + lane];
        idx = nbr[warp * KK + lane];
    }
    float wsum = w;
    #pragma unroll
    for (int o = 16; o >= 1; o >>= 1)
        wsum += __shfl_xor_sync(0xffffffffu, wsum, o);
    float weff = (wsum == 0.0f) ? (1.0f / KK) : (w / wsum);

    float4 a0 = make_float4(0.f, 0.f, 0.f, 0.f);
    float4 a1 = make_float4(0.f, 0.f, 0.f, 0.f);

    #pragma unroll
    for (int k = 0; k < KK; k++) {
        float wk = __shfl_sync(0xffffffffu, weff, k);
        int   nk = __shfl_sync(0xffffffffu, idx,  k);
        const float4* rp = reinterpret_cast<const float4*>(feats + (size_t)nk * DD);
        float4 f0 = __ldg(rp + lane);
        float4 f1 = __ldg(rp + lane + 32);
        a0.x += wk * f0.x; a0.y += wk * f0.y; a0.z += wk * f0.z; a0.w += wk * f0.w;
        a1.x += wk * f1.x; a1.y += wk * f1.y; a1.z += wk * f1.z; a1.w += wk * f1.w;
    }

    uint2* ah = reinterpret_cast<uint2*>(g_ah) + (size_t)warp * 64;
    uint2* al = reinterpret_cast<uint2*>(g_al) + (size_t)warp * 64;
    uint2 h, l;
    split2(a0.x, a0.y, h.x, l.x); split2(a0.z, a0.w, h.y, l.y);
    ah[lane] = h;  al[lane] = l;
    split2(a1.x, a1.y, h.x, l.x); split2(a1.z, a1.w, h.y, l.y);
    ah[32 + lane] = h;  al[32 + lane] = l;
}

// ---------------------------------------------------------------------------
// Kernel 2: HMMA GEMM (3-term bf16 split) + fused LayerNorm.
// Block 128x256, 512 threads = 4(m) x 4(n) warps, warp tile 32x64.
// cp.async DOUBLE-BUFFERED: two 96KB stages; prefetch chunk c+1 under the
// MMAs of chunk c. K chunks of 64, swizzled 128B rows feed ldmatrix.
// ---------------------------------------------------------------------------
#define STG      98304                 // stage stride: AH 16K | AL 16K | BH 32K | BL 32K
#define SOF_AL   16384
#define SOF_BH   32768
#define SOF_BL   65536
#define SMO_CONST (2 * STG)            // 196608: bias/gamma/beta 3 x 1KB
#define SMEM_TOTAL (SMO_CONST + 3072)  // 199680 B
// epilogue overlays stage0: psum float2[4][128] @0, stats float2[128] @4096

__global__ void __launch_bounds__(512) gemm_tc_kernel(
    const float* __restrict__ bias,
    const float* __restrict__ gamma,
    const float* __restrict__ beta,
    float* __restrict__ out)
{
    extern __shared__ char smem[];
    const uint32_t sb = smem_to_u32(smem);
    const int tid  = threadIdx.x;
    const int wid  = tid >> 5;
    const int lane = tid & 31;
    const int wm   = wid >> 2;          // 0..3 (m)
    const int wn   = wid & 3;           // 0..3 (n)
    const int row0 = blockIdx.x * 128;

    float* sC = reinterpret_cast<float*>(smem + SMO_CONST);
    if (tid < 256) {
        sC[tid]       = bias[tid];
        sC[256 + tid] = gamma[tid];
        sC[512 + tid] = beta[tid];
    }

    // per-thread tile-load geometry (shared by all chunk loads)
    const int ldr = tid >> 3;          // 0..63 row base step
    const int ldq = tid & 7;           // uint4 within 128B row
    const uint32_t so0 = SWZ((uint32_t)(ldr * 128 + ldq * 16));

    // ---- async chunk loader: A(128x64 hi/lo) + B(256x64 hi/lo) = 96 KB ----
    auto load_chunk = [&](int ch, int stg) {
        const uint32_t base = sb + stg * STG;
        #pragma unroll
        for (int i = 0; i < 2; i++) {                   // A: 64 rows per pass
            int r = ldr + i * 64;
            uint32_t so = SWZ((uint32_t)(r * 128 + ldq * 16));
            size_t gi = (size_t)(row0 + r) * 32 + ch * 8 + ldq;
            cpasync16(base + so,          &g_ah[gi]);
            cpasync16(base + SOF_AL + so, &g_al[gi]);
        }
        #pragma unroll
        for (int i = 0; i < 4; i++) {                   // B: 64 rows per pass
            int r = ldr + i * 64;
            uint32_t so = SWZ((uint32_t)(r * 128 + ldq * 16));
            size_t gi = (size_t)r * 32 + ch * 8 + ldq;
            cpasync16(base + SOF_BH + so, &g_wh[gi]);
            cpasync16(base + SOF_BL + so, &g_wl[gi]);
        }
        CP_COMMIT();
    };

    float c[2][8][4];
    #pragma unroll
    for (int i = 0; i < 2; i++)
        #pragma unroll
        for (int j = 0; j < 8; j++)
            #pragma unroll
            for (int q = 0; q < 4; q++) c[i][j][q] = 0.f;

    const int lrow = lane & 15;
    const int lkb  = (lane >> 4) * 16;

    load_chunk(0, 0);                    // prologue

    #pragma unroll
    for (int ch = 0; ch < 4; ch++) {
        if (ch + 1 < 4) load_chunk(ch + 1, (ch + 1) & 1);
        if (ch + 1 < 4) { CP_WAIT(1); } else { CP_WAIT(0); }
        __syncthreads();                 // chunk ch resident for all warps

        const uint32_t base = sb + (ch & 1) * STG;
        #pragma unroll
        for (int ks = 0; ks < 4; ks++) {
            const int kb = ks * 32 + lkb;
            uint32_t ah[2][4], al[2][4];
            #pragma unroll
            for (int mm = 0; mm < 2; mm++) {
                uint32_t off = SWZ((uint32_t)((wm * 32 + mm * 16 + lrow) * 128 + kb));
                ldsm_x4(base + off, ah[mm]);
                ldsm_x4(base + SOF_AL + off, al[mm]);
            }
            #pragma unroll
            for (int np = 0; np < 4; np++) {
                uint32_t off = SWZ((uint32_t)((wn * 64 + np * 16 + lrow) * 128 + kb));
                uint32_t bh[4], bl[4];
                ldsm_x4(base + SOF_BH + off, bh);
                ldsm_x4(base + SOF_BL + off, bl);
                #pragma unroll
                for (int sub = 0; sub < 2; sub++) {
                    int mn = np * 2 + sub;
                    #pragma unroll
                    for (int mm = 0; mm < 2; mm++) {
                        mma16816(c[mm][mn], ah[mm], bh[sub], bh[2 + sub]); // hi*hi
                        mma16816(c[mm][mn], ah[mm], bl[sub], bl[2 + sub]); // hi*lo
                        mma16816(c[mm][mn], al[mm], bh[sub], bh[2 + sub]); // lo*hi
                    }
                }
            }
        }
        __syncthreads();                 // all warps done with this stage
    }

    // ================= +bias, fused LayerNorm =================
    const int q2 = 2 * (lane & 3);
    #pragma unroll
    for (int mm = 0; mm < 2; mm++)
        #pragma unroll
        for (int mn = 0; mn < 8; mn++) {
            int col = wn * 64 + mn * 8 + q2;
            float b0 = sC[col], b1 = sC[col + 1];
            c[mm][mn][0] += b0; c[mm][mn][1] += b1;
            c[mm][mn][2] += b0; c[mm][mn][3] += b1;
        }

    float2* psum  = reinterpret_cast<float2*>(smem);          // [wn*128 + row]
    float2* stats = reinterpret_cast<float2*>(smem + 4096);   // [row]

    #pragma unroll
    for (int mm = 0; mm < 2; mm++) {
        #pragma unroll
        for (int h = 0; h < 2; h++) {
            float s = 0.f, s2 = 0.f;
            #pragma unroll
            for (int mn = 0; mn < 8; mn++) {
                float v0 = c[mm][mn][h * 2 + 0];
                float v1 = c[mm][mn][h * 2 + 1];
                s += v0 + v1;  s2 += v0 * v0 + v1 * v1;
            }
            s  += __shfl_xor_sync(0xffffffffu, s, 1);
            s  += __shfl_xor_sync(0xffffffffu, s, 2);
            s2 += __shfl_xor_sync(0xffffffffu, s2, 1);
            s2 += __shfl_xor_sync(0xffffffffu, s2, 2);
            if ((lane & 3) == 0) {
                int row = wm * 32 + mm * 16 + h * 8 + (lane >> 2);
                psum[wn * 128 + row] = make_float2(s, s2);
            }
        }
    }
    __syncthreads();

    if (tid < 128) {
        float s = 0.f, s2 = 0.f;
        #pragma unroll
        for (int p = 0; p < 4; p++) {
            float2 v = psum[p * 128 + tid];
            s += v.x;  s2 += v.y;
        }
        float mean = s * (1.0f / 256.0f);
        float var  = s2 * (1.0f / 256.0f) - mean * mean;
        stats[tid] = make_float2(mean, rsqrtf(var + LN_EPS));
    }
    __syncthreads();

    #pragma unroll
    for (int mm = 0; mm < 2; mm++)
        #pragma unroll
        for (int h = 0; h < 2; h++) {
            int row  = wm * 32 + mm * 16 + h * 8 + (lane >> 2);
            int grow = row0 + row;
            if (grow >= NN) continue;
            float2 st = stats[row];
            #pragma unroll
            for (int mn = 0; mn < 8; mn++) {
                int col = wn * 64 + mn * 8 + q2;
                float v0 = (c[mm][mn][h * 2 + 0] - st.x) * st.y * sC[256 + col]     + sC[512 + col];
                float v1 = (c[mm][mn][h * 2 + 1] - st.x) * st.y * sC[256 + col + 1] + sC[512 + col + 1];
                *reinterpret_cast<float2*>(out + (size_t)grow * DD + col) = make_float2(v0, v1);
            }
        }
}

// ---------------------------------------------------------------------------
extern "C" void kernel_launch(void* const* d_in, const int* in_sizes, int n_in,
                              void* d_out, int out_size)
{
    const float* feats = (const float*)d_in[0];
    const int*   nbr   = (const int*)d_in[1];    // int32 (JAX x64 disabled)
    const float* iw    = (const float*)d_in[2];
    const float* Wm    = (const float*)d_in[3];
    const float* bias  = (const float*)d_in[4];
    const float* gamma = (const float*)d_in[5];
    const float* beta  = (const float*)d_in[6];
    float*       out   = (float*)d_out;

    cudaFuncSetAttribute(gemm_tc_kernel,
                         cudaFuncAttributeMaxDynamicSharedMemorySize, SMEM_TOTAL);

    gather_kernel<<<6250, 256>>>(feats, nbr, iw, Wm);
    gemm_tc_kernel<<<NTILES, 512, SMEM_TOTAL>>>(bias, gamma, beta, out);
}